// round 2
// baseline (speedup 1.0000x reference)
#include <cuda_runtime.h>
#include <cub/cub.cuh>
#include <cstdint>

// Problem constants (B=8, L=1e6, C=4 -> size=1349)
#define SPIRAL_SIZE 1349
#define HALF        674
#define NCELL       (SPIRAL_SIZE * SPIRAL_SIZE)   // 1,819,801 < 2^21
#define SIGLEN      1000000
#define NBATCH      8
#define NRINGS      955            // rings 0..954 (max actual ring = rint(953.18) = 953)

#define PI_F 3.14159274101257324f  // fl(pi)

#define SORT_THREADS 512
#define SORT_ITEMS   9
#define SORT_CAP     (SORT_THREADS * SORT_ITEMS)  // 4608 >= max ring count (~4235 + lattice fluctuation)

__device__ uint32_t g_rank[NCELL];
__device__ int      g_ringTotal[NRINGS];
__device__ int      g_ringOffset[NRINGS];

extern "C" __device__ float __nv_atan2f(float, float);

// Exact float radius — identical op sequence to the validated round-1 kernel.
__device__ __forceinline__ float cell_r(int i, int j) {
    float x1 = (float)(j - HALF);
    float x2 = (float)(i - HALF);
    float rr = __fadd_rn(__fmul_rn(x1, x1), __fmul_rn(x2, x2));
    return __fsqrt_rn(rr);
}

// Bit-exact phi2 key (validated rel_err == 0.0 in round 1). Keys are all >= 0,
// so raw float bits are order-monotone as uint32.
__device__ __forceinline__ uint32_t cell_keybits(int i, int j) {
    float x1 = (float)(j - HALF);
    float x2 = (float)(i - HALF);
    float rr = __fadd_rn(__fmul_rn(x1, x1), __fmul_rn(x2, x2));
    float r  = __fsqrt_rn(rr);
    float xq = __fdiv_rn(x1, r);

    float phi;
    if (xq == -1.0f) {
        phi = PI_F;
    } else {
        // acos(x) = 2 * atan2(sqrt(1 - x*x), 1 + x)   (JAX lax.acos decomposition)
        float t  = __fsub_rn(1.0f, __fmul_rn(xq, xq));
        float sq = __fsqrt_rn(t);
        phi = __fmul_rn(2.0f, __nv_atan2f(sq, __fadd_rn(1.0f, xq)));
    }
    if (isnan(phi)) phi = 0.0f;

    float sgn = (x2 > 0.0f) ? 1.0f : ((x2 < 0.0f) ? -1.0f : 0.0f);
    phi = __fmul_rn(phi, sgn);
    if (x2 == 0.0f && x1 < 0.0f) phi = __fadd_rn(phi, PI_F);

    float phi2 = __fadd_rn(__fmul_rn(__fmul_rn(rintf(r), 2.0f), PI_F), phi);
    return __float_as_uint(phi2);
}

// Candidate |x1| interval for ring k on row i (annulus r in [k-0.5, k+0.5)),
// with +-2 integer slack so the exact rintf predicate decides membership.
__device__ __forceinline__ void row_bounds(int i, int k, int& amin, int& amax) {
    float x2  = (float)(i - HALF);
    float ro  = (float)k + 0.5f;
    float ri  = (float)k - 0.5f;
    float x22 = x2 * x2;
    float o2  = ro * ro - x22;
    if (o2 <= 0.0f) { amin = 1; amax = 0; return; }  // empty row
    float hi = sqrtf(o2);
    float i2 = ri * ri - x22;
    float lo = (i2 > 0.0f) ? sqrtf(i2) : 0.0f;
    int a0 = (int)lo - 2; if (a0 < 0)    a0 = 0;
    int a1 = (int)hi + 2; if (a1 > HALF) a1 = HALF;
    amin = a0; amax = a1;
}

// Enumerate ring-k members of row i in j-ascending order; calls F(i, j).
template <typename F>
__device__ __forceinline__ void enum_row(int i, int k, F&& f) {
    int amin, amax;
    row_bounds(i, k, amin, amax);
    for (int a = amax; a >= amin; a--) {            // x1 = -a  (j ascending)
        int j = HALF - a;
        if ((int)rintf(cell_r(i, j)) == k) f(i, j);
    }
    for (int a = (amin == 0 ? 1 : amin); a <= amax; a++) {  // x1 = +a
        int j = HALF + a;
        if ((int)rintf(cell_r(i, j)) == k) f(i, j);
    }
}

// K1: per-ring cell counts. One block per ring; contiguous row chunks per thread.
__global__ __launch_bounds__(SORT_THREADS) void ring_count_kernel() {
    int k = blockIdx.x;
    int t = threadIdx.x;
    int kk = min(k, HALF);
    int imin = HALF - kk;
    int nrows = 2 * kk + 1;
    int R = (nrows + SORT_THREADS - 1) / SORT_THREADS;

    int my = 0;
    for (int rr = 0; rr < R; rr++) {
        int i = imin + t * R + rr;
        if (i - imin < nrows)
            enum_row(i, k, [&](int, int) { my++; });
    }

    typedef cub::BlockReduce<int, SORT_THREADS> BR;
    __shared__ typename BR::TempStorage tmp;
    int tot = BR(tmp).Sum(my);
    if (t == 0) g_ringTotal[k] = tot;
}

// K2: exclusive scan of ring totals (single block).
__global__ void ring_scan_kernel() {
    typedef cub::BlockScan<int, 1024> BS;
    __shared__ typename BS::TempStorage tmp;
    int t = threadIdx.x;
    int v = (t < NRINGS) ? g_ringTotal[t] : 0;
    int out;
    BS(tmp).ExclusiveSum(v, out);
    if (t < NRINGS) g_ringOffset[t] = out;
}

// K3: per-ring sort. Stage packed (keybits << 21 | s) u64 keys, block radix
// sort bits [0,53) — low s bits make tie order deterministically index-stable,
// matching jnp.argsort's stable tie-break. Write rank[s] = ringOffset + pos.
__global__ __launch_bounds__(SORT_THREADS) void ring_sort_kernel() {
    int k = blockIdx.x;
    int t = threadIdx.x;

    typedef cub::BlockScan<int, SORT_THREADS> BS;
    typedef cub::BlockRadixSort<unsigned long long, SORT_THREADS, SORT_ITEMS> BRS;
    __shared__ union {
        unsigned long long staging[SORT_CAP];
        typename BRS::TempStorage sort;
    } u;
    __shared__ typename BS::TempStorage scan_tmp;

    int kk = min(k, HALF);
    int imin = HALF - kk;
    int nrows = 2 * kk + 1;
    int R = (nrows + SORT_THREADS - 1) / SORT_THREADS;

    // Phase A: per-thread member count over its contiguous row chunk.
    int my = 0;
    for (int rr = 0; rr < R; rr++) {
        int i = imin + t * R + rr;
        if (i - imin < nrows)
            enum_row(i, k, [&](int, int) { my++; });
    }

    int base, cnt;
    BS(scan_tmp).ExclusiveSum(my, base, cnt);

    // Phase B: re-enumerate, stage packed keys (order within ring irrelevant —
    // the packed index bits fully determine the sorted order).
    int pos = base;
    for (int rr = 0; rr < R; rr++) {
        int i = imin + t * R + rr;
        if (i - imin < nrows)
            enum_row(i, k, [&](int ii, int jj) {
                uint32_t kb = cell_keybits(ii, jj);
                uint32_t s  = (uint32_t)(ii * SPIRAL_SIZE + jj);
                u.staging[pos++] = ((unsigned long long)kb << 21) | s;
            });
    }
    __syncthreads();

    // Phase C: load blocked, pad with max, sort 53 bits.
    unsigned long long items[SORT_ITEMS];
#pragma unroll
    for (int it = 0; it < SORT_ITEMS; it++) {
        int p = t * SORT_ITEMS + it;
        items[it] = (p < cnt) ? u.staging[p] : 0xFFFFFFFFFFFFFFFFULL;
    }
    __syncthreads();
    BRS(u.sort).Sort(items, 0, 53);

    // Phase D: scatter ranks.
    int off = g_ringOffset[k];
#pragma unroll
    for (int it = 0; it < SORT_ITEMS; it++) {
        int p = t * SORT_ITEMS + it;
        if (p < cnt) {
            uint32_t s = (uint32_t)(items[it] & 0x1FFFFFu);
            g_rank[s] = (uint32_t)(off + p);
        }
    }
}

// K4: gather. out[b, s, :] = rank[s] < L ? in[b, rank[s], :] : 0
__global__ void spiral_gather_kernel(const float4* __restrict__ in,
                                     float4* __restrict__ out,
                                     const uint32_t* __restrict__ rank) {
    int s = blockIdx.x * blockDim.x + threadIdx.x;
    if (s >= NCELL) return;
    uint32_t r = rank[s];
    bool valid = (r < (uint32_t)SIGLEN);
    float4 z = make_float4(0.0f, 0.0f, 0.0f, 0.0f);
#pragma unroll
    for (int b = 0; b < NBATCH; b++) {
        float4 v = z;
        if (valid) v = __ldg(&in[(size_t)b * SIGLEN + r]);
        out[(size_t)b * NCELL + s] = v;
    }
}

extern "C" void kernel_launch(void* const* d_in, const int* in_sizes, int n_in,
                              void* d_out, int out_size) {
    (void)in_sizes; (void)n_in; (void)out_size;

    void* rankp;
    cudaGetSymbolAddress(&rankp, g_rank);

    ring_count_kernel<<<NRINGS, SORT_THREADS>>>();
    ring_scan_kernel<<<1, 1024>>>();
    ring_sort_kernel<<<NRINGS, SORT_THREADS>>>();

    const int T = 256;
    const int G = (NCELL + T - 1) / T;
    spiral_gather_kernel<<<G, T>>>((const float4*)d_in[0], (float4*)d_out,
                                   (const uint32_t*)rankp);
}

// round 3
// speedup vs baseline: 1.0299x; 1.0299x over previous
#include <cuda_runtime.h>
#include <cub/cub.cuh>
#include <cstdint>

// Problem constants (B=8, L=1e6, C=4 -> size=1349)
#define SPIRAL_SIZE 1349
#define HALF        674
#define NCELL       (SPIRAL_SIZE * SPIRAL_SIZE)   // 1,819,801 < 2^21
#define SIGLEN      1000000
#define NBATCH      8
#define NRINGS      955            // rings 0..954 (max actual ring = rint(953.18) = 953)

#define PI_F 3.14159274101257324f  // fl(pi)

#define RT   512                   // threads per ring block
#define CAP  4608                  // >= max ring population (~4235 at k=674)
#define NB   1024                  // key-bit buckets per ring

__device__ uint32_t g_rank[NCELL];      // packed (ring k << 13) | ring-local rank
__device__ int      g_ringTotal[NRINGS];
__device__ int      g_ringOffset[NRINGS];

extern "C" __device__ float __nv_atan2f(float, float);

// Exact float radius — identical op sequence to the validated kernels.
__device__ __forceinline__ float cell_r(int i, int j) {
    float x1 = (float)(j - HALF);
    float x2 = (float)(i - HALF);
    float rr = __fadd_rn(__fmul_rn(x1, x1), __fmul_rn(x2, x2));
    return __fsqrt_rn(rr);
}

// Bit-exact phi2 key (validated rel_err == 0.0). Keys all >= 0 -> raw float
// bits are order-monotone as uint32.
__device__ __forceinline__ uint32_t cell_keybits(int i, int j) {
    float x1 = (float)(j - HALF);
    float x2 = (float)(i - HALF);
    float rr = __fadd_rn(__fmul_rn(x1, x1), __fmul_rn(x2, x2));
    float r  = __fsqrt_rn(rr);
    float xq = __fdiv_rn(x1, r);

    float phi;
    if (xq == -1.0f) {
        phi = PI_F;
    } else {
        // acos(x) = 2 * atan2(sqrt(1 - x*x), 1 + x)  (JAX lax.acos decomposition)
        float t  = __fsub_rn(1.0f, __fmul_rn(xq, xq));
        float sq = __fsqrt_rn(t);
        phi = __fmul_rn(2.0f, __nv_atan2f(sq, __fadd_rn(1.0f, xq)));
    }
    if (isnan(phi)) phi = 0.0f;

    float sgn = (x2 > 0.0f) ? 1.0f : ((x2 < 0.0f) ? -1.0f : 0.0f);
    phi = __fmul_rn(phi, sgn);
    if (x2 == 0.0f && x1 < 0.0f) phi = __fadd_rn(phi, PI_F);

    float phi2 = __fadd_rn(__fmul_rn(__fmul_rn(rintf(r), 2.0f), PI_F), phi);
    return __float_as_uint(phi2);
}

// Candidate |x1| interval for ring k on row i, +-2 slack; exact rintf decides.
__device__ __forceinline__ void row_bounds(int i, int k, int& amin, int& amax) {
    float x2  = (float)(i - HALF);
    float ro  = (float)k + 0.5f;
    float ri  = (float)k - 0.5f;
    float x22 = x2 * x2;
    float o2  = ro * ro - x22;
    if (o2 <= 0.0f) { amin = 1; amax = 0; return; }
    float hi = sqrtf(o2);
    float i2 = ri * ri - x22;
    float lo = (i2 > 0.0f) ? sqrtf(i2) : 0.0f;
    int a0 = (int)lo - 2; if (a0 < 0)    a0 = 0;
    int a1 = (int)hi + 2; if (a1 > HALF) a1 = HALF;
    amin = a0; amax = a1;
}

template <typename F>
__device__ __forceinline__ void enum_row(int i, int k, F&& f) {
    int amin, amax;
    row_bounds(i, k, amin, amax);
    for (int a = amax; a >= amin; a--) {
        int j = HALF - a;
        if ((int)rintf(cell_r(i, j)) == k) f(i, j);
    }
    for (int a = (amin == 0 ? 1 : amin); a <= amax; a++) {
        int j = HALF + a;
        if ((int)rintf(cell_r(i, j)) == k) f(i, j);
    }
}

// ---------------------------------------------------------------------------
// K1: one block per ring. Bucket-counting rank:
//   A) histogram cells into NB monotone key-bit buckets
//   B) scan buckets, stage packed (keybits<<21 | s) into bucket slots
//   C) rank = bucketOffset + #{bucket peers with smaller packed value}
// Packed compare makes float-key ties index-stable — exactly jnp.argsort.
// Writes g_rank[s] = (k << 13) | ringLocalRank, and g_ringTotal[k].
// ---------------------------------------------------------------------------
__global__ __launch_bounds__(RT) void ring_rank_kernel() {
    __shared__ unsigned long long slots[CAP];   // 36,864 B
    __shared__ uint32_t cursor[NB];             //  4,096 B (hist, then cursor)
    __shared__ uint32_t boff[NB];               //  4,096 B (bucket offsets)
    __shared__ uint32_t warp_sums[16];
    __shared__ uint32_t s_total;

    const int k = blockIdx.x;
    const int t = threadIdx.x;

    for (int b = t; b < NB; b += RT) cursor[b] = 0;

    // Bucket mapping: monotone in key bits over this ring's key range.
    float twoPiK = __fmul_rn(__fmul_rn((float)k, 2.0f), PI_F);
    float lo_f   = __fsub_rn(twoPiK, PI_F); if (lo_f < 0.0f) lo_f = 0.0f;
    float hi_f   = __fadd_rn(twoPiK, PI_F);
    uint32_t lo_bits = __float_as_uint(lo_f);
    uint32_t span    = __float_as_uint(hi_f) - lo_bits;
    int bn = 32 - __clz(span | 1);
    int sh = (bn > 10) ? (bn - 10) : 0;

    int kk    = min(k, HALF);
    int imin  = HALF - kk;
    int nrows = 2 * kk + 1;
    int R     = (nrows + RT - 1) / RT;
    __syncthreads();

    // Phase A: histogram
    for (int rr = 0; rr < R; rr++) {
        int i = imin + t * R + rr;
        if (i - imin < nrows)
            enum_row(i, k, [&](int ii, int jj) {
                uint32_t kb = cell_keybits(ii, jj);
                atomicAdd(&cursor[(kb - lo_bits) >> sh], 1u);
            });
    }
    __syncthreads();

    // Exclusive scan of 1024 buckets (512 threads x 2)
    uint32_t c0 = cursor[2 * t], c1 = cursor[2 * t + 1];
    uint32_t v = c0 + c1;
    uint32_t lane = t & 31, warp = t >> 5;
    uint32_t x = v;
#pragma unroll
    for (int d = 1; d < 32; d <<= 1) {
        uint32_t y = __shfl_up_sync(0xFFFFFFFFu, x, d);
        if (lane >= d) x += y;
    }
    if (lane == 31) warp_sums[warp] = x;
    __syncthreads();
    if (warp == 0) {
        uint32_t w = (lane < 16) ? warp_sums[lane] : 0;
#pragma unroll
        for (int d = 1; d < 16; d <<= 1) {
            uint32_t y = __shfl_up_sync(0xFFFFFFFFu, w, d);
            if (lane >= d) w += y;
        }
        if (lane < 16) warp_sums[lane] = w;
    }
    __syncthreads();
    uint32_t warp_off = (warp > 0) ? warp_sums[warp - 1] : 0;
    uint32_t ex = warp_off + x - v;      // exclusive prefix at bucket 2t
    if (t == RT - 1) s_total = warp_off + x;
    __syncthreads();                     // everyone done reading cursor as hist
    boff[2 * t]     = ex;
    boff[2 * t + 1] = ex + c0;
    cursor[2 * t]     = ex;
    cursor[2 * t + 1] = ex + c0;
    __syncthreads();

    // Phase B: stage packed entries into bucket slots (arrival order arbitrary)
    for (int rr = 0; rr < R; rr++) {
        int i = imin + t * R + rr;
        if (i - imin < nrows)
            enum_row(i, k, [&](int ii, int jj) {
                uint32_t kb  = cell_keybits(ii, jj);
                uint32_t b   = (kb - lo_bits) >> sh;
                uint32_t s   = (uint32_t)(ii * SPIRAL_SIZE + jj);
                uint32_t pos = atomicAdd(&cursor[b], 1u);
                if (pos < CAP)
                    slots[pos] = ((unsigned long long)kb << 21) | s;
            });
    }
    __syncthreads();

    // Phase C: exact rank among bucket peers
    uint32_t total = s_total;
    for (uint32_t p = t; p < total; p += RT) {
        unsigned long long e = slots[p];
        uint32_t kb = (uint32_t)(e >> 21);
        uint32_t b  = (kb - lo_bits) >> sh;
        uint32_t start = boff[b];
        uint32_t rank = start;
        for (uint32_t q = start; q < total; q++) {
            unsigned long long f = slots[q];
            uint32_t bq = ((uint32_t)(f >> 21) - lo_bits) >> sh;
            if (bq != b) break;
            if (f < e) rank++;
        }
        uint32_t s = (uint32_t)(e & 0x1FFFFFu);
        g_rank[s] = ((uint32_t)k << 13) | rank;   // rank < CAP <= 2^13
    }
    if (t == 0) g_ringTotal[k] = (int)total;
}

// K2: exclusive scan of ring totals (single block).
__global__ void ring_scan_kernel() {
    typedef cub::BlockScan<int, 1024> BS;
    __shared__ typename BS::TempStorage tmp;
    int t = threadIdx.x;
    int v = (t < NRINGS) ? g_ringTotal[t] : 0;
    int out;
    BS(tmp).ExclusiveSum(v, out);
    if (t < NRINGS) g_ringOffset[t] = out;
}

// K3: gather. Decode packed rank, resolve global rank via ring offsets.
__global__ void spiral_gather_kernel(const float4* __restrict__ in,
                                     float4* __restrict__ out,
                                     const uint32_t* __restrict__ rank,
                                     const int* __restrict__ ringOff) {
    int s = blockIdx.x * blockDim.x + threadIdx.x;
    if (s >= NCELL) return;
    uint32_t v = rank[s];
    uint32_t k  = v >> 13;
    uint32_t rr = v & 8191u;
    uint32_t r  = (uint32_t)__ldg(&ringOff[k]) + rr;
    bool valid = (r < (uint32_t)SIGLEN);
    float4 z = make_float4(0.0f, 0.0f, 0.0f, 0.0f);
#pragma unroll
    for (int b = 0; b < NBATCH; b++) {
        float4 w = z;
        if (valid) w = __ldg(&in[(size_t)b * SIGLEN + r]);
        out[(size_t)b * NCELL + s] = w;
    }
}

extern "C" void kernel_launch(void* const* d_in, const int* in_sizes, int n_in,
                              void* d_out, int out_size) {
    (void)in_sizes; (void)n_in; (void)out_size;

    void *rankp, *offp;
    cudaGetSymbolAddress(&rankp, g_rank);
    cudaGetSymbolAddress(&offp,  g_ringOffset);

    ring_rank_kernel<<<NRINGS, RT>>>();
    ring_scan_kernel<<<1, 1024>>>();

    const int T = 256;
    const int G = (NCELL + T - 1) / T;
    spiral_gather_kernel<<<G, T>>>((const float4*)d_in[0], (float4*)d_out,
                                   (const uint32_t*)rankp,
                                   (const int*)offp);
}

// round 4
// speedup vs baseline: 2.3875x; 2.3183x over previous
#include <cuda_runtime.h>
#include <cub/cub.cuh>
#include <cstdint>

// Problem constants (B=8, L=1e6, C=4 -> size=1349)
#define SPIRAL_SIZE 1349
#define HALF        674
#define NCELL       (SPIRAL_SIZE * SPIRAL_SIZE)   // 1,819,801 < 2^21
#define SIGLEN      1000000
#define NBATCH      8

#define PI_F 3.14159274101257324f   // fl(pi)

// Validity cutoff: rings 0..564 fully cover rank < 1e6 (cum pop ~1.0012M);
// every cell in ring >= 565 has global rank > 1e6 -> zero-filled output.
#define KMAX   564
#define NRV    (KMAX + 1)           // 565 valid rings
#define BPR    4096                 // key-bit buckets per ring (load ~1)
#define NBKT   (NRV * BPR)          // 2,314,240

#define SCAN_BLK   512
#define SCAN_ITEMS 8
#define SCAN_TILE  (SCAN_BLK * SCAN_ITEMS)  // 4096
#define NTILES     (NBKT / SCAN_TILE)       // 565 (exact)

#define SORTCAP     1100000                 // > total valid cells (~1,001,200)
#define HALF_ROWS   (HALF + 1)              // rows i = HALF..1348 (x2 >= 0)
#define HALF_CELLS  (HALF_ROWS * SPIRAL_SIZE)  // 910,575

__device__ uint32_t           g_hist[NBKT];
__device__ uint32_t           g_cursor[NBKT];
__device__ uint32_t           g_kb[NCELL];
__device__ uint32_t           g_rank[NCELL];    // global rank, or 0xFFFFFFFF
__device__ unsigned long long g_sorted[SORTCAP];
__device__ uint32_t           g_lo[NRV];
__device__ int                g_sh[NRV];
__device__ uint32_t           g_part[NTILES];

extern "C" __device__ float __nv_atan2f(float, float);

// JAX acos: acos(x) = 2*atan2(sqrt(1-x*x), 1+x); exact pi at x==-1.
__device__ __forceinline__ float acos_jax(float xq) {
    if (xq == -1.0f) return PI_F;
    float t  = __fsub_rn(1.0f, __fmul_rn(xq, xq));
    float sq = __fsqrt_rn(t);
    return __fmul_rn(2.0f, __nv_atan2f(sq, __fadd_rn(1.0f, xq)));
}

// K0a: per-ring bucket tables. Keys of ring k lie in [T-pi, T+pi],
// T = fl(fl(2k)*pi); conservative bound +-3.2 guarantees containment.
__global__ void table_kernel() {
    int k = threadIdx.x;
    if (k >= NRV) return;
    float T   = __fmul_rn(__fmul_rn((float)k, 2.0f), PI_F);
    float lof = fmaxf(__fsub_rn(T, 3.2f), 0.0f);
    float hif = __fadd_rn(T, 3.2f);
    uint32_t lo   = __float_as_uint(lof);
    uint32_t span = __float_as_uint(hif) - lo;
    int bn = 32 - __clz(span | 1);
    g_lo[k] = lo;
    g_sh[k] = (bn > 12) ? (bn - 12) : 0;   // span>>sh < 4096
}

// K0b: zero the histogram (NBKT % 4 == 0).
__global__ void zero_kernel() {
    int t = blockIdx.x * blockDim.x + threadIdx.x;
    if (t < NBKT / 4) ((uint4*)g_hist)[t] = make_uint4(0, 0, 0, 0);
}

// ---------------------------------------------------------------------------
// K1: dense over the x2>=0 half-plane; one thread produces the key for its
// cell AND its mirror (x2 -> -x2), which is exactly fl(T - A) because r, xq,
// and A are bit-identical and phi*sign(x2) is an exact sign flip.
// Rings > KMAX get INVALID ranks and no key.
// ---------------------------------------------------------------------------
__global__ __launch_bounds__(256) void key_kernel() {
    int tid = blockIdx.x * blockDim.x + threadIdx.x;
    if (tid >= HALF_CELLS) return;
    int di = tid / SPIRAL_SIZE;          // 0..674
    int j  = tid - di * SPIRAL_SIZE;
    int i  = HALF + di;                  // x2 = di >= 0

    float x1 = (float)(j - HALF);
    float x2 = (float)di;
    float rr = __fadd_rn(__fmul_rn(x1, x1), __fmul_rn(x2, x2));
    float r  = __fsqrt_rn(rr);
    int   k  = (int)rintf(r);

    int s  = i * SPIRAL_SIZE + j;
    int sm = (2 * HALF - i) * SPIRAL_SIZE + j;

    if (k > KMAX) {
        g_rank[s] = 0xFFFFFFFFu;
        if (di > 0) g_rank[sm] = 0xFFFFFFFFu;
        return;
    }

    float T = __fmul_rn(__fmul_rn(rintf(r), 2.0f), PI_F);
    uint32_t lo = g_lo[k];
    int      sh = g_sh[k];
    uint32_t bb = (uint32_t)k * BPR;

    if (di == 0) {
        // x2 == 0 row: phi = A*0 = 0 (NaN-fixed for center), +pi if x1 < 0.
        float phi = (x1 < 0.0f) ? PI_F : 0.0f;
        uint32_t kb = __float_as_uint(__fadd_rn(T, phi));
        g_kb[s] = kb;
        atomicAdd(&g_hist[bb + ((kb - lo) >> sh)], 1u);
        return;
    }

    float A = acos_jax(__fdiv_rn(x1, r));   // finite: r > 0, x2 != 0

    uint32_t kb = __float_as_uint(__fadd_rn(T, A));     // x2 > 0: phi = +A
    g_kb[s] = kb;
    atomicAdd(&g_hist[bb + ((kb - lo) >> sh)], 1u);

    uint32_t kbm = __float_as_uint(__fadd_rn(T, -A));   // mirror: phi = -A
    g_kb[sm] = kbm;
    atomicAdd(&g_hist[bb + ((kbm - lo) >> sh)], 1u);
}

// ---------------------------------------------------------------------------
// Scan (3 kernels): exclusive prefix sum of g_hist -> g_cursor.
// Bucket id = k*BPR + sub is ring-major-monotone in the float key order, so
// the scan directly yields GLOBAL rank offsets.
// ---------------------------------------------------------------------------
__global__ __launch_bounds__(SCAN_BLK) void scanA_kernel() {
    typedef cub::BlockReduce<uint32_t, SCAN_BLK> BR;
    __shared__ typename BR::TempStorage tmp;
    int base = blockIdx.x * SCAN_TILE + threadIdx.x * SCAN_ITEMS;
    uint4 a = ((const uint4*)g_hist)[base / 4];
    uint4 b = ((const uint4*)g_hist)[base / 4 + 1];
    uint32_t v = a.x + a.y + a.z + a.w + b.x + b.y + b.z + b.w;
    uint32_t tot = BR(tmp).Sum(v);
    if (threadIdx.x == 0) g_part[blockIdx.x] = tot;
}

__global__ void scanB_kernel() {
    typedef cub::BlockScan<uint32_t, 1024> BS;
    __shared__ typename BS::TempStorage tmp;
    int t = threadIdx.x;
    uint32_t v = (t < NTILES) ? g_part[t] : 0;
    uint32_t out;
    BS(tmp).ExclusiveSum(v, out);
    if (t < NTILES) g_part[t] = out;
}

__global__ __launch_bounds__(SCAN_BLK) void scanC_kernel() {
    typedef cub::BlockScan<uint32_t, SCAN_BLK> BS;
    __shared__ typename BS::TempStorage tmp;
    int base = blockIdx.x * SCAN_TILE + threadIdx.x * SCAN_ITEMS;
    uint4 a = ((const uint4*)g_hist)[base / 4];
    uint4 b = ((const uint4*)g_hist)[base / 4 + 1];
    uint32_t it[SCAN_ITEMS] = {a.x, a.y, a.z, a.w, b.x, b.y, b.z, b.w};
    uint32_t sum = 0;
#pragma unroll
    for (int q = 0; q < SCAN_ITEMS; q++) sum += it[q];
    uint32_t tb;
    BS(tmp).ExclusiveSum(sum, tb);
    tb += g_part[blockIdx.x];
    uint4 oa, ob;
    uint32_t run = tb;
    oa.x = run; run += it[0]; oa.y = run; run += it[1];
    oa.z = run; run += it[2]; oa.w = run; run += it[3];
    ob.x = run; run += it[4]; ob.y = run; run += it[5];
    ob.z = run; run += it[6]; ob.w = run;
    ((uint4*)g_cursor)[base / 4]     = oa;
    ((uint4*)g_cursor)[base / 4 + 1] = ob;
}

// K3: scatter packed (kb<<21 | s) into bucket slots (order within a bucket
// is arbitrary; ranks are resolved by value in K4).
__global__ __launch_bounds__(256) void scatter_kernel() {
    int s = blockIdx.x * blockDim.x + threadIdx.x;
    if (s >= NCELL) return;
    int i = s / SPIRAL_SIZE, j = s - i * SPIRAL_SIZE;
    float x1 = (float)(j - HALF), x2 = (float)(i - HALF);
    float r = __fsqrt_rn(__fadd_rn(__fmul_rn(x1, x1), __fmul_rn(x2, x2)));
    int k = (int)rintf(r);
    if (k > KMAX) return;
    uint32_t kb = g_kb[s];
    uint32_t b  = (uint32_t)k * BPR + ((kb - g_lo[k]) >> g_sh[k]);
    uint32_t pos = atomicAdd(&g_cursor[b], 1u);
    g_sorted[pos] = ((unsigned long long)kb << 21) | (uint32_t)s;
}

// K4: exact global rank = bucketStart + #{bucket peers with smaller packed
// value}. Packed low bits = flat index -> index-stable ties == jnp.argsort.
// bucketStart = g_cursor[b] - g_hist[b] (cursor finished at start+count).
__global__ __launch_bounds__(256) void rank_kernel() {
    int s = blockIdx.x * blockDim.x + threadIdx.x;
    if (s >= NCELL) return;
    int i = s / SPIRAL_SIZE, j = s - i * SPIRAL_SIZE;
    float x1 = (float)(j - HALF), x2 = (float)(i - HALF);
    float r = __fsqrt_rn(__fadd_rn(__fmul_rn(x1, x1), __fmul_rn(x2, x2)));
    int k = (int)rintf(r);
    if (k > KMAX) return;
    uint32_t kb  = g_kb[s];
    uint32_t b   = (uint32_t)k * BPR + ((kb - g_lo[k]) >> g_sh[k]);
    uint32_t end = g_cursor[b];
    uint32_t st  = end - g_hist[b];
    unsigned long long my = ((unsigned long long)kb << 21) | (uint32_t)s;
    uint32_t rank = st;
    for (uint32_t q = st; q < end; q++)
        rank += (g_sorted[q] < my) ? 1u : 0u;
    g_rank[s] = rank;
}

// K5: gather. out[b,s,:] = rank[s] < L ? in[b,rank[s],:] : 0.
// Streaming stores (__stcs) keep L2 capacity for the scattered input reads.
__global__ __launch_bounds__(256) void gather_kernel(
        const float4* __restrict__ in, float4* __restrict__ out,
        const uint32_t* __restrict__ rank) {
    int s = blockIdx.x * blockDim.x + threadIdx.x;
    if (s >= NCELL) return;
    uint32_t r = rank[s];
    bool valid = (r < (uint32_t)SIGLEN);
    float4 z = make_float4(0.0f, 0.0f, 0.0f, 0.0f);
#pragma unroll
    for (int b = 0; b < NBATCH; b++) {
        float4 w = z;
        if (valid) w = __ldg(&in[(size_t)b * SIGLEN + r]);
        __stcs(&out[(size_t)b * NCELL + s], w);
    }
}

extern "C" void kernel_launch(void* const* d_in, const int* in_sizes, int n_in,
                              void* d_out, int out_size) {
    (void)in_sizes; (void)n_in; (void)out_size;

    void* rankp;
    cudaGetSymbolAddress(&rankp, g_rank);

    table_kernel<<<1, NRV>>>();
    zero_kernel<<<(NBKT / 4 + 255) / 256, 256>>>();
    key_kernel<<<(HALF_CELLS + 255) / 256, 256>>>();
    scanA_kernel<<<NTILES, SCAN_BLK>>>();
    scanB_kernel<<<1, 1024>>>();
    scanC_kernel<<<NTILES, SCAN_BLK>>>();

    const int G = (NCELL + 255) / 256;
    scatter_kernel<<<G, 256>>>();
    rank_kernel<<<G, 256>>>();
    gather_kernel<<<G, 256>>>((const float4*)d_in[0], (float4*)d_out,
                              (const uint32_t*)rankp);
}

// round 5
// speedup vs baseline: 2.6017x; 1.0897x over previous
#include <cuda_runtime.h>
#include <cub/cub.cuh>
#include <cstdint>

// Problem constants (B=8, L=1e6, C=4 -> size=1349)
#define SPIRAL_SIZE 1349
#define HALF        674
#define NCELL       (SPIRAL_SIZE * SPIRAL_SIZE)   // 1,819,801 < 2^21
#define SIGLEN      1000000
#define NBATCH      8

#define PI_F 3.14159274101257324f   // fl(pi)

// Validity cutoff (validated rel_err==0.0): rings 0..564 cover all ranks < 1e6;
// every cell with rint(r) >= 565 lands past rank 1e6 -> zero-filled output.
#define KMAX   564
#define NRV    (KMAX + 1)           // 565 valid rings
#define BPR    2048                 // key-bit buckets per ring (max ring pop ~3544)
#define NBKT   (NRV * BPR)          // 1,157,120

#define SCAN_BLK   512
#define SCAN_ITEMS 4
#define SCAN_TILE  (SCAN_BLK * SCAN_ITEMS)  // 2048
#define NTILES     (NBKT / SCAN_TILE)       // 565 (exact)

#define SORTCAP     1100000                 // > total valid cells (~1,001,200)
#define HALF_ROWS   (HALF + 1)
#define HALF_CELLS  (HALF_ROWS * SPIRAL_SIZE)  // 910,575

__device__ uint32_t           g_hist[NBKT];
__device__ uint32_t           g_cursor[NBKT];
__device__ uint32_t           g_kb[NCELL];
__device__ unsigned long long g_sorted[SORTCAP];
__device__ uint32_t           g_part[NTILES];

extern "C" __device__ float __nv_atan2f(float, float);

// JAX acos: acos(x) = 2*atan2(sqrt(1-x*x), 1+x); exact pi at x==-1.
__device__ __forceinline__ float acos_jax(float xq) {
    if (xq == -1.0f) return PI_F;
    float t  = __fsub_rn(1.0f, __fmul_rn(xq, xq));
    float sq = __fsqrt_rn(t);
    return __fmul_rn(2.0f, __nv_atan2f(sq, __fadd_rn(1.0f, xq)));
}

// Per-ring bucket mapping (inline, ~8 ops). Keys of ring k lie in
// [T-pi, T+pi], T = fl(2k * pi); bound +-3.2 guarantees containment.
// Monotone: (kb - lo) >> sh, result < 2048.
__device__ __forceinline__ void ring_map(int k, uint32_t& lo, int& sh) {
    float T   = __fmul_rn((float)(2 * k), PI_F);
    float lof = fmaxf(__fsub_rn(T, 3.2f), 0.0f);
    float hif = __fadd_rn(T, 3.2f);
    lo = __float_as_uint(lof);
    uint32_t span = __float_as_uint(hif) - lo;
    int bn = 32 - __clz(span | 1);
    sh = (bn > 11) ? (bn - 11) : 0;
}

// K0: zero the histogram (NBKT % 4 == 0).
__global__ void zero_kernel() {
    int t = blockIdx.x * blockDim.x + threadIdx.x;
    if (t < NBKT / 4) ((uint4*)g_hist)[t] = make_uint4(0, 0, 0, 0);
}

// ---------------------------------------------------------------------------
// K1: dense over the x2>=0 half-plane; one thread produces the key for its
// cell AND its mirror (x2 -> -x2): r, xq, A are bit-identical and
// phi*sign(x2) is an exact sign flip, so mirror key = fl(T - A).
// ---------------------------------------------------------------------------
__global__ __launch_bounds__(256) void key_kernel() {
    int tid = blockIdx.x * blockDim.x + threadIdx.x;
    if (tid >= HALF_CELLS) return;
    int di = tid / SPIRAL_SIZE;          // 0..674
    int j  = tid - di * SPIRAL_SIZE;
    int i  = HALF + di;

    float x1 = (float)(j - HALF);
    float x2 = (float)di;
    float rr = __fadd_rn(__fmul_rn(x1, x1), __fmul_rn(x2, x2));
    float r  = __fsqrt_rn(rr);
    int   k  = (int)rintf(r);
    if (k > KMAX) return;                // invalid: fused gather detects by k

    float T = __fmul_rn(__fmul_rn(rintf(r), 2.0f), PI_F);
    uint32_t lo; int sh;
    ring_map(k, lo, sh);
    uint32_t bb = (uint32_t)k * BPR;

    int s  = i * SPIRAL_SIZE + j;

    if (di == 0) {
        // x2 == 0 row: phi = 0 (acos finite * sign(0), NaN-fixed center), +pi if x1<0.
        float phi = (x1 < 0.0f) ? PI_F : 0.0f;
        uint32_t kb = __float_as_uint(__fadd_rn(T, phi));
        g_kb[s] = kb;
        atomicAdd(&g_hist[bb + ((kb - lo) >> sh)], 1u);
        return;
    }

    float A = acos_jax(__fdiv_rn(x1, r));   // finite: r > 0 here

    uint32_t kb = __float_as_uint(__fadd_rn(T, A));     // x2 > 0: phi = +A
    g_kb[s] = kb;
    atomicAdd(&g_hist[bb + ((kb - lo) >> sh)], 1u);

    int sm = (2 * HALF - i) * SPIRAL_SIZE + j;
    uint32_t kbm = __float_as_uint(__fadd_rn(T, -A));   // mirror: phi = -A
    g_kb[sm] = kbm;
    atomicAdd(&g_hist[bb + ((kbm - lo) >> sh)], 1u);
}

// ---------------------------------------------------------------------------
// Scan (3 kernels): exclusive prefix sum of g_hist -> g_cursor. Bucket id
// k*BPR + sub is globally monotone in float key order, so the scan yields
// GLOBAL rank offsets directly.
// ---------------------------------------------------------------------------
__global__ __launch_bounds__(SCAN_BLK) void scanA_kernel() {
    typedef cub::BlockReduce<uint32_t, SCAN_BLK> BR;
    __shared__ typename BR::TempStorage tmp;
    int base = blockIdx.x * SCAN_TILE + threadIdx.x * SCAN_ITEMS;
    uint4 a = ((const uint4*)g_hist)[base / 4];
    uint32_t tot = BR(tmp).Sum(a.x + a.y + a.z + a.w);
    if (threadIdx.x == 0) g_part[blockIdx.x] = tot;
}

__global__ void scanB_kernel() {
    typedef cub::BlockScan<uint32_t, 1024> BS;
    __shared__ typename BS::TempStorage tmp;
    int t = threadIdx.x;
    uint32_t v = (t < NTILES) ? g_part[t] : 0;
    uint32_t out;
    BS(tmp).ExclusiveSum(v, out);
    if (t < NTILES) g_part[t] = out;
}

__global__ __launch_bounds__(SCAN_BLK) void scanC_kernel() {
    typedef cub::BlockScan<uint32_t, SCAN_BLK> BS;
    __shared__ typename BS::TempStorage tmp;
    int base = blockIdx.x * SCAN_TILE + threadIdx.x * SCAN_ITEMS;
    uint4 a = ((const uint4*)g_hist)[base / 4];
    uint32_t sum = a.x + a.y + a.z + a.w;
    uint32_t tb;
    BS(tmp).ExclusiveSum(sum, tb);
    tb += g_part[blockIdx.x];
    uint4 o;
    o.x = tb; tb += a.x;
    o.y = tb; tb += a.y;
    o.z = tb; tb += a.z;
    o.w = tb;
    ((uint4*)g_cursor)[base / 4] = o;
}

// K3: scatter packed (kb<<21 | s) into bucket slots (in-bucket order is
// arbitrary; ranks are resolved by value in the fused gather).
__global__ __launch_bounds__(256) void scatter_kernel() {
    int s = blockIdx.x * blockDim.x + threadIdx.x;
    if (s >= NCELL) return;
    int i = s / SPIRAL_SIZE, j = s - i * SPIRAL_SIZE;
    float x1 = (float)(j - HALF), x2 = (float)(i - HALF);
    float r = __fsqrt_rn(__fadd_rn(__fmul_rn(x1, x1), __fmul_rn(x2, x2)));
    int k = (int)rintf(r);
    if (k > KMAX) return;
    uint32_t lo; int sh;
    ring_map(k, lo, sh);
    uint32_t kb = g_kb[s];
    uint32_t b  = (uint32_t)k * BPR + ((kb - lo) >> sh);
    uint32_t pos = atomicAdd(&g_cursor[b], 1u);
    g_sorted[pos] = ((unsigned long long)kb << 21) | (uint32_t)s;
}

// ---------------------------------------------------------------------------
// K4 (fused rank + gather): per cell, recompute k; invalid -> zeros. Else
// rank = bucketStart + #{bucket peers with smaller packed value} (index-
// stable ties == jnp.argsort), bucketStart = cursor[b] - hist[b].
// Streaming stores keep L2 capacity for the scattered input reads.
// ---------------------------------------------------------------------------
__global__ __launch_bounds__(256) void gather_kernel(
        const float4* __restrict__ in, float4* __restrict__ out) {
    int s = blockIdx.x * blockDim.x + threadIdx.x;
    if (s >= NCELL) return;
    int i = s / SPIRAL_SIZE, j = s - i * SPIRAL_SIZE;
    float x1 = (float)(j - HALF), x2 = (float)(i - HALF);
    float r = __fsqrt_rn(__fadd_rn(__fmul_rn(x1, x1), __fmul_rn(x2, x2)));
    int k = (int)rintf(r);

    bool valid = (k <= KMAX);
    uint32_t rank = 0xFFFFFFFFu;
    if (valid) {
        uint32_t lo; int sh;
        ring_map(k, lo, sh);
        uint32_t kb  = g_kb[s];
        uint32_t b   = (uint32_t)k * BPR + ((kb - lo) >> sh);
        uint32_t end = g_cursor[b];
        uint32_t cnt = g_hist[b];
        uint32_t st  = end - cnt;
        rank = st;
        if (cnt > 1) {
            unsigned long long my = ((unsigned long long)kb << 21) | (uint32_t)s;
            for (uint32_t q = st; q < end; q++)
                rank += (g_sorted[q] < my) ? 1u : 0u;
        }
        valid = (rank < (uint32_t)SIGLEN);
    }

    float4 z = make_float4(0.0f, 0.0f, 0.0f, 0.0f);
#pragma unroll
    for (int b = 0; b < NBATCH; b++) {
        float4 w = z;
        if (valid) w = __ldg(&in[(size_t)b * SIGLEN + rank]);
        __stcs(&out[(size_t)b * NCELL + s], w);
    }
}

extern "C" void kernel_launch(void* const* d_in, const int* in_sizes, int n_in,
                              void* d_out, int out_size) {
    (void)in_sizes; (void)n_in; (void)out_size;

    zero_kernel<<<(NBKT / 4 + 255) / 256, 256>>>();
    key_kernel<<<(HALF_CELLS + 255) / 256, 256>>>();
    scanA_kernel<<<NTILES, SCAN_BLK>>>();
    scanB_kernel<<<1, 1024>>>();
    scanC_kernel<<<NTILES, SCAN_BLK>>>();

    const int G = (NCELL + 255) / 256;
    scatter_kernel<<<G, 256>>>();
    gather_kernel<<<G, 256>>>((const float4*)d_in[0], (float4*)d_out);
}